// round 5
// baseline (speedup 1.0000x reference)
#include <cuda_runtime.h>
#include <cstdint>

#define BB      8
#define CTOT    256
#define HH      96
#define WW      128
#define TH      2                  // rows per block
#define ROWT    (HH/TH)            // 48
#define THREADS 288                // 9 warps, one dy each
#define CHS     (HH*WW)            // channel stride in floats (12288)
#define UNR     8                  // channels per unrolled group

typedef unsigned long long ull;

// Zero region for OOB loads. Inner unrolled offsets walk up to (UNR-1)*CHS+8
// floats past the base; zero-strided pointers stay inside this buffer.
#define ZPAD_F4 ((7*CHS + 64)/4 + 16)          // ~21536 float4 = ~344KB
__device__ float4 zeroPad[ZPAD_F4];

__global__ void zero_pad_kernel() {
    int i = blockIdx.x * blockDim.x + threadIdx.x;
    if (i < ZPAD_F4) zeroPad[i] = make_float4(0.f, 0.f, 0.f, 0.f);
}

__device__ __forceinline__ ull pk(float lo, float hi) {
    ull r;
    asm("mov.b64 %0, {%1,%2};" : "=l"(r) : "f"(lo), "f"(hi));
    return r;
}
__device__ __forceinline__ float2 upk(ull v) {
    float2 f;
    asm("mov.b64 {%0,%1}, %2;" : "=f"(f.x), "=f"(f.y) : "l"(v));
    return f;
}
__device__ __forceinline__ void ffma2(ull& d, ull a, ull b) {
    asm("fma.rn.f32x2 %0, %1, %2, %0;" : "+l"(d) : "l"(a), "l"(b));
}

__global__ void __launch_bounds__(THREADS, 2)
corr_kernel(const float* __restrict__ in1, const float* __restrict__ in2,
            float* __restrict__ out)
{
    const int tid  = threadIdx.x;
    const int warp = tid >> 5;         // dy 0..8
    const int lane = tid & 31;
    const int r    = lane >> 4;        // row within tile (0/1)
    const int g    = lane & 15;        // 8-px group
    const int x0   = g << 3;

    const int bx = blockIdx.x;
    const int b  = bx / ROWT;
    const int h0 = (bx - b * ROWT) * TH;

    const int hB = h0 + r + warp - 4;  // in2 source row for this half-warp
    const bool rowOK = (hB >= 0) && (hB < HH);

    // Base pointers (channel 0). B window covers floats [x0-4, x0+11]:
    //   Q0 @ x0-4 (left edge, OOB when g==0)  -> pBL
    //   Q1 @ x0, Q2 @ x0+4 (always in-range)  -> pBM
    //   Q3 @ x0+8 (right edge, OOB when g==15)-> pBR
    const float* pA = in1 + (size_t)(b * CTOT) * CHS + (h0 + r) * WW + x0;
    const float* zp = (const float*)zeroPad;
    const float* base2 = rowOK
        ? in2 + (size_t)(b * CTOT) * CHS + hB * WW + x0 : zp;
    const bool okL = rowOK && (g > 0);
    const bool okR = rowOK && (g < 15);
    const float* pBL = okL   ? base2 - 4 : zp;
    const float* pBM = rowOK ? base2     : zp;
    const float* pBR = okR   ? base2 + 8 : zp;
    const int sBM = rowOK ? UNR * CHS : 0;
    const int sBL = okL   ? UNR * CHS : 0;
    const int sBR = okR   ? UNR * CHS : 0;

    ull acc[9][4];
#pragma unroll
    for (int d = 0; d < 9; d++)
#pragma unroll
        for (int t = 0; t < 4; t++) acc[d][t] = 0ull;

    for (int c0 = 0; c0 < CTOT; c0 += UNR) {
#pragma unroll
        for (int k = 0; k < UNR; k++) {
            const int o = k * CHS;
            float4 a0 = __ldg((const float4*)(pA  + o));
            float4 a1 = __ldg((const float4*)(pA  + o + 4));
            float4 q0 = __ldg((const float4*)(pBL + o));
            float4 q1 = __ldg((const float4*)(pBM + o));
            float4 q2 = __ldg((const float4*)(pBM + o + 4));
            float4 q3 = __ldg((const float4*)(pBR + o));

            ull A[4];
            A[0] = pk(a0.x, a0.y); A[1] = pk(a0.z, a0.w);
            A[2] = pk(a1.x, a1.y); A[3] = pk(a1.z, a1.w);

            float f[16] = { q0.x, q0.y, q0.z, q0.w,  q1.x, q1.y, q1.z, q1.w,
                            q2.x, q2.y, q2.z, q2.w,  q3.x, q3.y, q3.z, q3.w };
            ull E[8], O[7];
#pragma unroll
            for (int j = 0; j < 8; j++) E[j] = pk(f[2 * j], f[2 * j + 1]);
#pragma unroll
            for (int j = 0; j < 7; j++) O[j] = pk(f[2 * j + 1], f[2 * j + 2]);

#pragma unroll
            for (int d = 0; d < 9; d++) {
#pragma unroll
                for (int t = 0; t < 4; t++) {
                    ull bo = (d & 1) ? O[t + (d >> 1)] : E[t + (d >> 1)];
                    ffma2(acc[d][t], A[t], bo);
                }
            }
        }
        pA  += UNR * CHS;
        pBL += sBL;
        pBM += sBM;
        pBR += sBR;
    }

    // Epilogue: out[b, warp*9+d, h0+r, x0..x0+7] = acc / 256
    const float inv = 1.0f / 256.0f;
    const int hOut = h0 + r;
#pragma unroll
    for (int d = 0; d < 9; d++) {
        const int n = warp * 9 + d;
        float* op = out + ((size_t)((b * 81 + n) * HH + hOut)) * WW + x0;
        float2 u0 = upk(acc[d][0]);
        float2 u1 = upk(acc[d][1]);
        float2 u2 = upk(acc[d][2]);
        float2 u3 = upk(acc[d][3]);
        *(float4*)op       = make_float4(u0.x * inv, u0.y * inv, u1.x * inv, u1.y * inv);
        *(float4*)(op + 4) = make_float4(u2.x * inv, u2.y * inv, u3.x * inv, u3.y * inv);
    }
}

extern "C" void kernel_launch(void* const* d_in, const int* in_sizes, int n_in,
                              void* d_out, int out_size)
{
    const float* in1 = (const float*)d_in[0];
    const float* in2 = (const float*)d_in[1];
    float* out = (float*)d_out;

    zero_pad_kernel<<<(ZPAD_F4 + 255) / 256, 256>>>();
    corr_kernel<<<BB * ROWT, THREADS>>>(in1, in2, out);
}

// round 6
// speedup vs baseline: 2.7170x; 2.7170x over previous
#include <cuda_runtime.h>
#include <cstdint>

#define BB      8
#define CTOT    256
#define HH      96
#define WW      128
#define ROWT    HH                 // one output row per block
#define CCK     8                  // channels per chunk
#define NCHUNK  (CTOT/CCK)         // 32
#define THREADS 288                // 9 warps, one dy each
#define CHS     (HH*WW)            // channel stride (floats)

#define ROWB      576                          // bytes per halo row (136 used, padded)
#define WARP_SEG  (CCK*ROWB)                   // 4608 B per warp per buffer
#define BUF_BYTES (9*WARP_SEG)                 // 41472
#define SMEM_TOTAL (2*BUF_BYTES)               // 82944 -> 2 blocks/SM

typedef unsigned long long ull;

__device__ __forceinline__ float4 lds128(uint32_t addr) {
    float4 v;
    asm volatile("ld.shared.v4.f32 {%0,%1,%2,%3}, [%4];"
                 : "=f"(v.x), "=f"(v.y), "=f"(v.z), "=f"(v.w) : "r"(addr));
    return v;
}
__device__ __forceinline__ void sts_zero16(uint32_t addr) {
    asm volatile("st.shared.v4.b32 [%0], {%1,%1,%1,%1};" :: "r"(addr), "r"(0) : "memory");
}
__device__ __forceinline__ void cpa16(uint32_t dst, const float* src) {
    asm volatile("cp.async.cg.shared.global [%0], [%1], 16;" :: "r"(dst), "l"(src));
}
__device__ __forceinline__ ull pk(float lo, float hi) {
    ull r;
    asm("mov.b64 %0, {%1,%2};" : "=l"(r) : "f"(lo), "f"(hi));
    return r;
}
__device__ __forceinline__ float2 upk(ull v) {
    float2 f;
    asm("mov.b64 {%0,%1}, %2;" : "=f"(f.x), "=f"(f.y) : "l"(v));
    return f;
}
__device__ __forceinline__ void ffma2(ull& d, ull a, ull b) {
    asm("fma.rn.f32x2 %0, %1, %2, %0;" : "+l"(d) : "l"(a), "l"(b));
}

// Warp-private loader: this warp's halo row, CCK channels, lane = 16B chunk.
// Always commits (keeps per-warp group counting uniform even when row is OOB).
__device__ __forceinline__ void load_chunk(uint32_t wbuf, const float* srcRow,
                                           int lane, bool rowOK)
{
    if (rowOK) {
        const uint32_t dst0 = wbuf + (uint32_t)(16 + lane * 16);
        const float* s = srcRow + lane * 4;
#pragma unroll
        for (int c = 0; c < CCK; c++)
            cpa16(dst0 + c * ROWB, s + (size_t)c * CHS);
    }
    asm volatile("cp.async.commit_group;" ::: "memory");
}

__device__ __forceinline__ void compute_chunk(uint32_t wbuf, const float* pA,
                                              uint32_t offB, ull acc[9][2])
{
#pragma unroll
    for (int cc = 0; cc < CCK; cc++) {
        float4 qa = __ldg((const float4*)(pA + (size_t)cc * CHS));
        const uint32_t rb = wbuf + cc * ROWB + offB;
        float4 q0 = lds128(rb);
        float4 q1 = lds128(rb + 16);
        float4 q2 = lds128(rb + 32);

        ull A0 = pk(qa.x, qa.y);
        ull A1 = pk(qa.z, qa.w);

        float f[12] = { q0.x, q0.y, q0.z, q0.w,
                        q1.x, q1.y, q1.z, q1.w,
                        q2.x, q2.y, q2.z, q2.w };
        ull E[6], O[5];
#pragma unroll
        for (int j = 0; j < 6; j++) E[j] = pk(f[2 * j], f[2 * j + 1]);
#pragma unroll
        for (int j = 0; j < 5; j++) O[j] = pk(f[2 * j + 1], f[2 * j + 2]);

#pragma unroll
        for (int d = 0; d < 9; d++) {
            ull b0 = (d & 1) ? O[(d >> 1)]     : E[(d >> 1)];
            ull b1 = (d & 1) ? O[(d >> 1) + 1] : E[(d >> 1) + 1];
            ffma2(acc[d][0], A0, b0);
            ffma2(acc[d][1], A1, b1);
        }
    }
}

__global__ void __launch_bounds__(THREADS, 2)
corr_kernel(const float* __restrict__ in1, const float* __restrict__ in2,
            float* __restrict__ out)
{
    extern __shared__ char smem[];
    const uint32_t smem32 = (uint32_t)__cvta_generic_to_shared(smem);

    const int tid  = threadIdx.x;
    const int warp = tid >> 5;         // dy 0..8
    const int lane = tid & 31;
    const int x0   = lane << 2;        // 4 px per lane

    const int bx = blockIdx.x;
    const int b  = bx / ROWT;
    const int h0 = bx - b * ROWT;      // output row

    const int hB = h0 + warp - 4;      // this warp's in2 source row
    const bool rowOK = (hB >= 0) && (hB < HH);

    // Warp-private smem segments (two buffers)
    const uint32_t wb0 = smem32 + (uint32_t)(warp * WARP_SEG);
    const uint32_t wb1 = wb0 + BUF_BYTES;
    // B window for lane: floats [x0-4 .. x0+11] -> byte 16*lane within a row
    const uint32_t offB = (uint32_t)(16 * lane);

    // Lane-local pre-zero (reader == writer; no sync needed).
#pragma unroll
    for (int buf = 0; buf < 2; buf++) {
        const uint32_t wb = (buf ? wb1 : wb0);
#pragma unroll
        for (int cc = 0; cc < CCK; cc++) {
            const uint32_t rb = wb + cc * ROWB;
            if (!rowOK) {
                sts_zero16(rb + offB);
                sts_zero16(rb + offB + 16);
                sts_zero16(rb + offB + 32);
            } else {
                if (lane == 0)  sts_zero16(rb);          // left pad (floats -4..-1)
                if (lane == 31) sts_zero16(rb + 528);    // right pad (floats 128..131)
            }
        }
    }

    const float* pA = in1 + (size_t)(b * CTOT) * CHS + h0 * WW + x0;
    const float* srcRow = rowOK
        ? in2 + (size_t)(b * CTOT) * CHS + hB * WW : (const float*)0;

    ull acc[9][2];
#pragma unroll
    for (int d = 0; d < 9; d++) { acc[d][0] = 0ull; acc[d][1] = 0ull; }

    load_chunk(wb0, srcRow, lane, rowOK);

    for (int k = 0; k < NCHUNK; k++) {
        if (k + 1 < NCHUNK) {
            load_chunk((k + 1) & 1 ? wb1 : wb0,
                       rowOK ? srcRow + (size_t)(k + 1) * CCK * CHS : srcRow,
                       lane, rowOK);
            asm volatile("cp.async.wait_group 1;" ::: "memory");
        } else {
            asm volatile("cp.async.wait_group 0;" ::: "memory");
        }
        compute_chunk((k & 1) ? wb1 : wb0, pA + (size_t)k * CCK * CHS, offB, acc);
    }

    // Epilogue: out[b, warp*9+d, h0, x0..x0+3] = acc / 256
    const float inv = 1.0f / 256.0f;
#pragma unroll
    for (int d = 0; d < 9; d++) {
        const int n = warp * 9 + d;
        float* op = out + ((size_t)((b * 81 + n) * HH + h0)) * WW + x0;
        float2 u0 = upk(acc[d][0]);
        float2 u1 = upk(acc[d][1]);
        *(float4*)op = make_float4(u0.x * inv, u0.y * inv, u1.x * inv, u1.y * inv);
    }
}

extern "C" void kernel_launch(void* const* d_in, const int* in_sizes, int n_in,
                              void* d_out, int out_size)
{
    const float* in1 = (const float*)d_in[0];
    const float* in2 = (const float*)d_in[1];
    float* out = (float*)d_out;

    cudaFuncSetAttribute(corr_kernel, cudaFuncAttributeMaxDynamicSharedMemorySize, SMEM_TOTAL);
    corr_kernel<<<BB * ROWT, THREADS, SMEM_TOTAL>>>(in1, in2, out);
}

// round 7
// speedup vs baseline: 2.8254x; 1.0399x over previous
#include <cuda_runtime.h>
#include <cstdint>

#define BB      8
#define CTOT    256
#define HH      96
#define WW      128
#define ROWT    HH                 // one output row per block
#define CCK     4                  // channels per chunk
#define NCHUNK  (CTOT/CCK)         // 64
#define NBUF    3                  // triple buffer, prefetch depth 2
#define THREADS 288                // 9 warps, one dy each
#define CHS     (HH*WW)            // channel stride (floats)

#define ROWB      576                          // bytes per halo row (136 used, padded)
#define WARP_SEG  (CCK*ROWB)                   // 2304 B per warp per buffer
#define BUF_BYTES (9*WARP_SEG)                 // 20736
#define SMEM_TOTAL (NBUF*BUF_BYTES)            // 62208 -> 3 blocks/SM

typedef unsigned long long ull;

__device__ __forceinline__ float4 lds128(uint32_t addr) {
    float4 v;
    asm volatile("ld.shared.v4.f32 {%0,%1,%2,%3}, [%4];"
                 : "=f"(v.x), "=f"(v.y), "=f"(v.z), "=f"(v.w) : "r"(addr));
    return v;
}
__device__ __forceinline__ void sts_zero16(uint32_t addr) {
    asm volatile("st.shared.v4.b32 [%0], {%1,%1,%1,%1};" :: "r"(addr), "r"(0) : "memory");
}
__device__ __forceinline__ void cpa16(uint32_t dst, const float* src) {
    asm volatile("cp.async.cg.shared.global [%0], [%1], 16;" :: "r"(dst), "l"(src));
}
__device__ __forceinline__ ull pk(float lo, float hi) {
    ull r;
    asm("mov.b64 %0, {%1,%2};" : "=l"(r) : "f"(lo), "f"(hi));
    return r;
}
__device__ __forceinline__ float2 upk(ull v) {
    float2 f;
    asm("mov.b64 {%0,%1}, %2;" : "=f"(f.x), "=f"(f.y) : "l"(v));
    return f;
}
__device__ __forceinline__ void ffma2(ull& d, ull a, ull b) {
    asm("fma.rn.f32x2 %0, %1, %2, %0;" : "+l"(d) : "l"(a), "l"(b));
}

// Warp-private loader: this warp's halo row, CCK channels, lane = 16B chunk.
// Always commits (keeps per-warp group counting uniform even when row is OOB).
__device__ __forceinline__ void load_chunk(uint32_t wbuf, const float* srcRow,
                                           int lane, bool rowOK)
{
    if (rowOK) {
        const uint32_t dst0 = wbuf + (uint32_t)(16 + lane * 16);
        const float* s = srcRow + lane * 4;
#pragma unroll
        for (int c = 0; c < CCK; c++)
            cpa16(dst0 + c * ROWB, s + (size_t)c * CHS);
    }
    asm volatile("cp.async.commit_group;" ::: "memory");
}

__device__ __forceinline__ void compute_chunk(uint32_t wbuf, const float* pA,
                                              uint32_t offB, ull acc[9][2])
{
#pragma unroll
    for (int cc = 0; cc < CCK; cc++) {
        float4 qa = __ldg((const float4*)(pA + (size_t)cc * CHS));
        const uint32_t rb = wbuf + cc * ROWB + offB;
        float4 q0 = lds128(rb);
        float4 q1 = lds128(rb + 16);
        float4 q2 = lds128(rb + 32);

        ull A0 = pk(qa.x, qa.y);
        ull A1 = pk(qa.z, qa.w);

        float f[12] = { q0.x, q0.y, q0.z, q0.w,
                        q1.x, q1.y, q1.z, q1.w,
                        q2.x, q2.y, q2.z, q2.w };
        ull E[6], O[5];
#pragma unroll
        for (int j = 0; j < 6; j++) E[j] = pk(f[2 * j], f[2 * j + 1]);
#pragma unroll
        for (int j = 0; j < 5; j++) O[j] = pk(f[2 * j + 1], f[2 * j + 2]);

#pragma unroll
        for (int d = 0; d < 9; d++) {
            ull b0 = (d & 1) ? O[(d >> 1)]     : E[(d >> 1)];
            ull b1 = (d & 1) ? O[(d >> 1) + 1] : E[(d >> 1) + 1];
            ffma2(acc[d][0], A0, b0);
            ffma2(acc[d][1], A1, b1);
        }
    }
}

__global__ void __launch_bounds__(THREADS, 3)
corr_kernel(const float* __restrict__ in1, const float* __restrict__ in2,
            float* __restrict__ out)
{
    extern __shared__ char smem[];
    const uint32_t smem32 = (uint32_t)__cvta_generic_to_shared(smem);

    const int tid  = threadIdx.x;
    const int warp = tid >> 5;         // dy 0..8
    const int lane = tid & 31;
    const int x0   = lane << 2;        // 4 px per lane

    const int bx = blockIdx.x;
    const int b  = bx / ROWT;
    const int h0 = bx - b * ROWT;      // output row

    const int hB = h0 + warp - 4;      // this warp's in2 source row
    const bool rowOK = (hB >= 0) && (hB < HH);

    // Warp-private smem segments, NBUF buffers
    uint32_t wb[NBUF];
#pragma unroll
    for (int i = 0; i < NBUF; i++)
        wb[i] = smem32 + (uint32_t)(i * BUF_BYTES + warp * WARP_SEG);
    // B window for lane: floats [x0-4 .. x0+11] -> byte 16*lane within a row
    const uint32_t offB = (uint32_t)(16 * lane);

    // Lane-local pre-zero (reader == writer; no sync needed).
#pragma unroll
    for (int buf = 0; buf < NBUF; buf++) {
#pragma unroll
        for (int cc = 0; cc < CCK; cc++) {
            const uint32_t rb = wb[buf] + cc * ROWB;
            if (!rowOK) {
                sts_zero16(rb + offB);
                sts_zero16(rb + offB + 16);
                sts_zero16(rb + offB + 32);
            } else {
                if (lane == 0)  sts_zero16(rb);          // left pad (floats -4..-1)
                if (lane == 31) sts_zero16(rb + 528);    // right pad (floats 128..131)
            }
        }
    }

    const float* pA = in1 + (size_t)(b * CTOT) * CHS + h0 * WW + x0;
    const float* srcRow = rowOK
        ? in2 + (size_t)(b * CTOT) * CHS + hB * WW : (const float*)0;

    ull acc[9][2];
#pragma unroll
    for (int d = 0; d < 9; d++) { acc[d][0] = 0ull; acc[d][1] = 0ull; }

    // Prologue: fill two buffers (groups k=0, k=1 pending)
    load_chunk(wb[0], srcRow, lane, rowOK);
    load_chunk(wb[1], rowOK ? srcRow + (size_t)CCK * CHS : srcRow, lane, rowOK);

    int cur = 0, nxt = 2;
    for (int k = 0; k < NCHUNK; k++) {
        if (k + 2 < NCHUNK) {
            load_chunk(wb[nxt],
                       rowOK ? srcRow + (size_t)(k + 2) * CCK * CHS : srcRow,
                       lane, rowOK);
            asm volatile("cp.async.wait_group 2;" ::: "memory");
        } else if (k + 1 < NCHUNK) {
            asm volatile("cp.async.wait_group 1;" ::: "memory");
        } else {
            asm volatile("cp.async.wait_group 0;" ::: "memory");
        }
        compute_chunk(wb[cur], pA + (size_t)k * CCK * CHS, offB, acc);
        cur = (cur == NBUF - 1) ? 0 : cur + 1;
        nxt = (nxt == NBUF - 1) ? 0 : nxt + 1;
    }

    // Epilogue: out[b, warp*9+d, h0, x0..x0+3] = acc / 256
    const float inv = 1.0f / 256.0f;
#pragma unroll
    for (int d = 0; d < 9; d++) {
        const int n = warp * 9 + d;
        float* op = out + ((size_t)((b * 81 + n) * HH + h0)) * WW + x0;
        float2 u0 = upk(acc[d][0]);
        float2 u1 = upk(acc[d][1]);
        *(float4*)op = make_float4(u0.x * inv, u0.y * inv, u1.x * inv, u1.y * inv);
    }
}

extern "C" void kernel_launch(void* const* d_in, const int* in_sizes, int n_in,
                              void* d_out, int out_size)
{
    const float* in1 = (const float*)d_in[0];
    const float* in2 = (const float*)d_in[1];
    float* out = (float*)d_out;

    cudaFuncSetAttribute(corr_kernel, cudaFuncAttributeMaxDynamicSharedMemorySize, SMEM_TOTAL);
    corr_kernel<<<BB * ROWT, THREADS, SMEM_TOTAL>>>(in1, in2, out);
}